// round 2
// baseline (speedup 1.0000x reference)
#include <cuda_runtime.h>
#include <math.h>

// KoLeoLoss — analytic reduction of the flat-stride-diagonal variant, fused
// into a single launch with a grid-wide spin barrier.
//
// Math recap (n=1024, d=256): the reference's flat[::n+1]=inf over the
// flattened (n,n,d) tensor excludes the self-pair ONLY at feature k=0
// (f = i*d*(n+1) + k ≡ k mod 1025), and for k=0 excludes exactly j=i
// (gcd(d, n+1)=1, n ≡ -1 mod n+1). So m[i,k]=0 exactly for k>=1 and
// m[i,0] = min_{j!=i} |y_j - y_i| with y = L2-normalized column 0.
//
//   loss = -( sum_i log(NN_i + eps) + n*(d-1)*log(eps) ) / n
//
// Single kernel, 128 blocks x 256 threads (one wave on 148 SMs => all CTAs
// co-resident, spin barrier is safe):
//   Phase A: warp-per-row sumsq (2x float4 per lane), write g_y[row].
//   Barrier: one spinner thread per block on an atomic counter.
//   Phase B: warp-per-i NN over the 4KB g_y array (L1 resident), log,
//            Q32.32 fixed-point atomic accumulate (order-independent =>
//            deterministic), last block writes out and resets state.

#define KN   1024
#define KD   256
#define KEPS 1e-8f
#define NBLK 128
#define NTHR 256   // 8 warps

__device__ float               g_y[KN];
__device__ int                 g_cnt1 = 0;
__device__ int                 g_cnt2 = 0;
__device__ unsigned long long  g_sum  = 0ull;

__global__ void __launch_bounds__(NTHR, 1)
koleo_fused_kernel(const float* __restrict__ X, float* __restrict__ out) {
    const int t    = threadIdx.x;
    const int w    = t >> 5;
    const int lane = t & 31;
    const int b    = blockIdx.x;

    // ---------------- Phase A: row norms -> g_y ----------------
    const int row = b * 8 + w;
    const float4* Xr = (const float4*)(X + row * KD);
    float4 a = Xr[lane];        // cols [4*lane, 4*lane+4)
    float4 c = Xr[lane + 32];   // cols [128+4*lane, ...)
    float ss = a.x*a.x + a.y*a.y + a.z*a.z + a.w*a.w
             + c.x*c.x + c.y*c.y + c.z*c.z + c.w*c.w;
    #pragma unroll
    for (int o = 16; o > 0; o >>= 1)
        ss += __shfl_xor_sync(0xFFFFFFFFu, ss, o);
    if (lane == 0) {
        float norm = sqrtf(ss);
        g_y[row] = a.x / fmaxf(norm, KEPS);   // a.x == X[row*KD + 0] for lane 0
    }
    __syncthreads();

    // ---------------- Grid barrier ----------------
    if (t == 0) {
        __threadfence();                       // publish g_y stores
        atomicAdd(&g_cnt1, 1);
        while (atomicAdd(&g_cnt1, 0) < NBLK) __nanosleep(32);
    }
    __syncthreads();
    __threadfence();                           // acquire side

    // ---------------- Phase B: 1-D NN on g_y ----------------
    const int i  = b * 8 + w;
    const float xi = g_y[i];
    float m = INFINITY;
    #pragma unroll
    for (int r = 0; r < 32; r++) {
        const int j = r * 32 + lane;
        const float dd = fabsf(g_y[j] - xi);
        if (j != i) m = fminf(m, dd);
    }
    #pragma unroll
    for (int o = 16; o > 0; o >>= 1)
        m = fminf(m, __shfl_xor_sync(0xFFFFFFFFu, m, o));
    if (lane == 0) {
        const float l = logf(m + KEPS);
        // Q32.32 fixed point: order-independent integer accumulation.
        const long long q = (long long)((double)l * 4294967296.0);
        atomicAdd(&g_sum, (unsigned long long)q);
    }
    __syncthreads();

    // ---------------- Completion: last block finalizes ----------------
    if (t == 0) {
        __threadfence();
        const int old = atomicAdd(&g_cnt2, 1);
        if (old == NBLK - 1) {
            const unsigned long long s = atomicAdd(&g_sum, 0ull);
            const double sum_logs = (double)(long long)s / 4294967296.0;
            const double cterm = (double)(KN * (KD - 1)) * (double)logf(KEPS);
            out[0] = (float)(-(sum_logs + cterm) / (double)KN);
            // Reset state for the next graph replay.
            g_sum  = 0ull;
            g_cnt1 = 0;
            g_cnt2 = 0;
            __threadfence();
        }
    }
}

extern "C" void kernel_launch(void* const* d_in, const int* in_sizes, int n_in,
                              void* d_out, int out_size) {
    (void)in_sizes; (void)n_in; (void)out_size;
    const float* X = (const float*)d_in[0];
    float* out = (float*)d_out;
    koleo_fused_kernel<<<NBLK, NTHR>>>(X, out);
}

// round 3
// speedup vs baseline: 1.0148x; 1.0148x over previous
#include <cuda_runtime.h>
#include <math.h>

// KoLeoLoss — analytic reduction of the flat-stride-diagonal variant.
//
// Math recap (n=1024, d=256): the reference's flat[::n+1]=inf over the
// flattened (n,n,d) tensor excludes the self-pair ONLY at feature k=0,
// and for k=0 excludes exactly j=i. So m[i,k]=0 exactly for k>=1 and
// m[i,0] = min_{j!=i} |y_j - y_i| with y = L2-normalized column 0.
//
//   loss = -( sum_i log(NN_i + eps) + n*(d-1)*log(eps) ) / n
//
// Two kernels (a graph edge is a cheaper grid barrier than an L2 spin):
//   K1: warp-per-row sumsq (2x float4/lane) -> g_y[1024].
//   K2: smem-staged 1-D NN, warp-per-i, Q32.32 fixed-point block sums
//       (order-independent => deterministic), one atomicAdd per block,
//       last-arriving block finalizes out and resets state.

#define KN   1024
#define KD   256
#define KEPS 1e-8f
#define NBLK 128
#define NTHR 256   // 8 warps

__device__ float               g_y[KN];
__device__ int                 g_done = 0;
__device__ unsigned long long  g_sum  = 0ull;

__global__ void __launch_bounds__(NTHR, 1)
koleo_rownorm_kernel(const float* __restrict__ X) {
    const int t    = threadIdx.x;
    const int w    = t >> 5;
    const int lane = t & 31;
    const int row  = blockIdx.x * 8 + w;

    const float4* Xr = (const float4*)(X + row * KD);
    float4 a = Xr[lane];        // lane 0: a.x == X[row*KD + 0]
    float4 c = Xr[lane + 32];
    float ss = a.x*a.x + a.y*a.y + a.z*a.z + a.w*a.w
             + c.x*c.x + c.y*c.y + c.z*c.z + c.w*c.w;
    #pragma unroll
    for (int o = 16; o > 0; o >>= 1)
        ss += __shfl_xor_sync(0xFFFFFFFFu, ss, o);
    if (lane == 0) {
        float norm = sqrtf(ss);
        g_y[row] = a.x / fmaxf(norm, KEPS);
    }
}

__global__ void __launch_bounds__(NTHR, 1)
koleo_nn_kernel(float* __restrict__ out) {
    const int t    = threadIdx.x;
    const int w    = t >> 5;
    const int lane = t & 31;
    const int i    = blockIdx.x * 8 + w;

    // Stage all of g_y (4 KB) into smem: 256 threads x 1 float4.
    __shared__ float sy[KN];
    __shared__ long long psum[8];
    ((float4*)sy)[t] = ((const float4*)g_y)[t];
    __syncthreads();

    const float xi = sy[i];
    float m = INFINITY;
    #pragma unroll
    for (int r = 0; r < 32; r++) {
        const int j = r * 32 + lane;          // stride-1 within warp: conflict-free
        const float dd = fabsf(sy[j] - xi);
        if (j != i) m = fminf(m, dd);
    }
    #pragma unroll
    for (int o = 16; o > 0; o >>= 1)
        m = fminf(m, __shfl_xor_sync(0xFFFFFFFFu, m, o));
    if (lane == 0) {
        const float l = logf(m + KEPS);
        psum[w] = (long long)((double)l * 4294967296.0);   // Q32.32
    }
    __syncthreads();

    if (t == 0) {
        long long blk = 0;
        #pragma unroll
        for (int k = 0; k < 8; k++) blk += psum[k];
        atomicAdd(&g_sum, (unsigned long long)blk);
        __threadfence();
        const int old = atomicAdd(&g_done, 1);
        if (old == NBLK - 1) {
            // All 127 other blocks' g_sum contributions are ordered before
            // their g_done increments; we observed the last increment.
            const unsigned long long s = atomicAdd(&g_sum, 0ull);
            const double sum_logs = (double)(long long)s / 4294967296.0;
            const double cterm = (double)(KN * (KD - 1)) * log((double)KEPS);
            out[0] = (float)(-(sum_logs + cterm) / (double)KN);
            // Reset for next graph replay.
            g_sum  = 0ull;
            g_done = 0;
            __threadfence();
        }
    }
}

extern "C" void kernel_launch(void* const* d_in, const int* in_sizes, int n_in,
                              void* d_out, int out_size) {
    (void)in_sizes; (void)n_in; (void)out_size;
    const float* X = (const float*)d_in[0];
    float* out = (float*)d_out;
    koleo_rownorm_kernel<<<NBLK, NTHR>>>(X);
    koleo_nn_kernel<<<NBLK, NTHR>>>(out);
}